// round 14
// baseline (speedup 1.0000x reference)
#include <cuda_runtime.h>
#include <cuda_fp16.h>

// ============================================================================
// SRU cell. L=2048, B=16, D=1024.
//   u = x @ W  -> fp16 mma.sync (chain-4 fp16 partials, fp32 every 2 kt).
//   OVERLAP: single GEMM launch + concurrent scan on stream2; scan consumes
//   m-blocks as GEMM publishes them via device progress counters.
// ============================================================================

#define L_DIM 2048
#define B_DIM 16
#define D_DIM 1024
#define N_DIM 3072
#define K_DIM 1024
#define M_DIM 32768  // L*B

#define BM 128
#define BN 128
#define BK 32
#define STAGES 4
#define ROWSTR_H 40
#define KT (K_DIM / BK)
#define STAGE_H (2 * BM * ROWSTR_H)
#define GEMM_SMEM_BYTES (STAGES * STAGE_H * 2) // 81920
#define NBLK_X (N_DIM / BN)                    // 24 n-blocks per m-block
#define NBLK_Y (M_DIM / BM)                    // 256 m-blocks

#define LOG2E 1.4426950408889634f

// Scratch (allocation-free rule: __device__ globals)
__device__ __half g_Xh[(size_t)M_DIM * K_DIM];  // X fp16 (64 MB)
__device__ __half g_Wh[N_DIM * K_DIM];          // W^T fp16 (6 MB)
__device__ __half g_Uh[(size_t)M_DIM * N_DIM];  // GEMM output u, fp16 (201 MB)
__device__ unsigned g_cnt[NBLK_Y];              // m-block progress counters

// ---------------------------------------------------------------------------
__device__ __forceinline__ unsigned smem_u32(const void* p) {
    unsigned a;
    asm("{ .reg .u64 t; cvta.to.shared.u64 t, %1; cvt.u32.u64 %0, t; }" : "=r"(a) : "l"(p));
    return a;
}

__device__ __forceinline__ void cp_async16(unsigned dst, const void* src) {
    asm volatile("cp.async.cg.shared.global [%0], [%1], 16;" :: "r"(dst), "l"(src));
}

__device__ __forceinline__ void ldmatrix_x4(unsigned& r0, unsigned& r1,
                                            unsigned& r2, unsigned& r3, unsigned addr) {
    asm volatile("ldmatrix.sync.aligned.m8n8.x4.shared.b16 {%0,%1,%2,%3}, [%4];"
                 : "=r"(r0), "=r"(r1), "=r"(r2), "=r"(r3) : "r"(addr));
}

__device__ __forceinline__ void mma_f16c(unsigned& c0, unsigned& c1,
                                         const unsigned* a, const unsigned* b) {
    asm volatile(
        "mma.sync.aligned.m16n8k16.row.col.f16.f16.f16.f16 "
        "{%0,%1}, {%2,%3,%4,%5}, {%6,%7}, {%0,%1};"
        : "+r"(c0), "+r"(c1)
        : "r"(a[0]), "r"(a[1]), "r"(a[2]), "r"(a[3]), "r"(b[0]), "r"(b[1]));
}

__device__ __forceinline__ float ex2f(float x) {
    float r; asm("ex2.approx.f32 %0, %1;" : "=f"(r) : "f"(x)); return r;
}
__device__ __forceinline__ float rcpf(float x) {
    float r; asm("rcp.approx.f32 %0, %1;" : "=f"(r) : "f"(x)); return r;
}

// Scan-side wait: m-block `blk` is ready when all NBLK_X n-CTAs arrived.
__device__ __forceinline__ void wait_mblock(int blk) {
    volatile unsigned* p = ((volatile unsigned*)g_cnt) + blk;
    while (*p < (unsigned)NBLK_X) { __nanosleep(64); }
    __threadfence();
}

// ---------------------------------------------------------------------------
// Kernel A: zero progress counters (must precede GEMM and scan each replay)
// ---------------------------------------------------------------------------
__global__ void init_cnt() { g_cnt[threadIdx.x] = 0u; }

// ---------------------------------------------------------------------------
// Kernel 0: convert X -> fp16
// ---------------------------------------------------------------------------
__global__ void __launch_bounds__(256) convert_x(const float* __restrict__ X) {
    size_t i = ((size_t)blockIdx.x * 256 + threadIdx.x) * 8;
    float4 a = *(const float4*)(X + i);
    float4 b = *(const float4*)(X + i + 4);
    __half2 h0 = __floats2half2_rn(a.x, a.y);
    __half2 h1 = __floats2half2_rn(a.z, a.w);
    __half2 h2 = __floats2half2_rn(b.x, b.y);
    __half2 h3 = __floats2half2_rn(b.z, b.w);
    uint4 o;
    o.x = *(unsigned*)&h0; o.y = *(unsigned*)&h1;
    o.z = *(unsigned*)&h2; o.w = *(unsigned*)&h3;
    *(uint4*)(g_Xh + i) = o;
}

// ---------------------------------------------------------------------------
// Kernel 1: transpose W (K,N) -> W^T (N,K) fp16
// ---------------------------------------------------------------------------
__global__ void transpose_w(const float* __restrict__ W) {
    __shared__ float t[32][33];
    int n0 = blockIdx.x * 32, k0 = blockIdx.y * 32;
    int tx = threadIdx.x, ty = threadIdx.y;  // 32 x 8
#pragma unroll
    for (int i = 0; i < 32; i += 8)
        t[ty + i][tx] = W[(size_t)(k0 + ty + i) * N_DIM + n0 + tx];
    __syncthreads();
#pragma unroll
    for (int i = 0; i < 32; i += 8)
        g_Wh[(size_t)(n0 + ty + i) * K_DIM + k0 + tx] = __float2half_rn(t[tx][ty + i]);
}

// ---------------------------------------------------------------------------
// Kernel 2: fp16 GEMM (R12 mainloop) + progress publication per m-block.
// ---------------------------------------------------------------------------
__global__ void __launch_bounds__(256) gemm_f16() {
    extern __shared__ __half smem_h[];
    unsigned sbase = smem_u32(smem_h);

    int tid = threadIdx.x;
    int wid = tid >> 5;
    int lid = tid & 31;
    int g   = lid >> 2;
    int t4  = lid & 3;
    int q   = lid >> 3;
    int rr  = lid & 7;
    int warp_m = wid >> 1;
    int warp_n = wid & 1;
    int mbase = warp_m * 32;
    int nbase = warp_n * 64;

    int n0 = blockIdx.x * BN;
    int m0 = blockIdx.y * BM;

    const __half* Arow = g_Xh + (size_t)m0 * K_DIM;
    const __half* Brow = g_Wh + (size_t)n0 * K_DIM;
    const int B_OFF_H = BM * ROWSTR_H;

    float acc[2][8][4];
    unsigned cc0[2][8], cc1[2][8];
#pragma unroll
    for (int mt = 0; mt < 2; mt++)
#pragma unroll
        for (int nt = 0; nt < 8; nt++) {
#pragma unroll
            for (int i = 0; i < 4; i++) acc[mt][nt][i] = 0.0f;
            cc0[mt][nt] = 0u; cc1[mt][nt] = 0u;
        }

    auto load_stage = [&](int stage, int kc) {
        unsigned sA = sbase + (unsigned)(stage * STAGE_H) * 2u;
        unsigned sB = sA + (unsigned)B_OFF_H * 2u;
#pragma unroll
        for (int t = 0; t < 2; t++) {
            int j = tid + t * 256;
            int row = j >> 2;
            int c = j & 3;
            unsigned off = (unsigned)(row * ROWSTR_H + c * 8) * 2u;
            cp_async16(sA + off, Arow + (size_t)row * K_DIM + kc + c * 8);
            cp_async16(sB + off, Brow + (size_t)row * K_DIM + kc + c * 8);
        }
        asm volatile("cp.async.commit_group;" ::: "memory");
    };

#pragma unroll
    for (int s = 0; s < STAGES - 1; s++) load_stage(s, s * BK);

    for (int kt = 0; kt < KT; kt++) {
        asm volatile("cp.async.wait_group %0;" :: "n"(STAGES - 2) : "memory");
        __syncthreads();

        if (kt + STAGES - 1 < KT)
            load_stage((kt + STAGES - 1) % STAGES, (kt + STAGES - 1) * BK);
        else
            asm volatile("cp.async.commit_group;" ::: "memory");

        unsigned stA = sbase + (unsigned)((kt % STAGES) * STAGE_H) * 2u;
        unsigned stB = stA + (unsigned)B_OFF_H * 2u;

        unsigned a[2][2][4];
        unsigned b[2][8][2];
#pragma unroll
        for (int kk = 0; kk < 2; kk++) {
#pragma unroll
            for (int mt = 0; mt < 2; mt++) {
                int row = mbase + mt * 16 + ((q & 1) << 3) + rr;
                int kh  = kk * 16 + (q >> 1) * 8;
                ldmatrix_x4(a[kk][mt][0], a[kk][mt][1], a[kk][mt][2], a[kk][mt][3],
                            stA + (unsigned)(row * ROWSTR_H + kh) * 2u);
            }
#pragma unroll
            for (int nt2 = 0; nt2 < 4; nt2++) {
                int row = nbase + nt2 * 16 + ((q >> 1) << 3) + rr;
                int kh  = kk * 16 + (q & 1) * 8;
                ldmatrix_x4(b[kk][nt2 * 2][0], b[kk][nt2 * 2][1],
                            b[kk][nt2 * 2 + 1][0], b[kk][nt2 * 2 + 1][1],
                            stB + (unsigned)(row * ROWSTR_H + kh) * 2u);
            }
        }

#pragma unroll
        for (int mt = 0; mt < 2; mt++)
#pragma unroll
            for (int nt = 0; nt < 8; nt++) {
                mma_f16c(cc0[mt][nt], cc1[mt][nt], a[0][mt], b[0][nt]);
                mma_f16c(cc0[mt][nt], cc1[mt][nt], a[1][mt], b[1][nt]);
            }

        if (kt & 1) {
#pragma unroll
            for (int mt = 0; mt < 2; mt++)
#pragma unroll
                for (int nt = 0; nt < 8; nt++) {
                    float2 f0 = __half22float2(*(__half2*)&cc0[mt][nt]);
                    float2 f1 = __half22float2(*(__half2*)&cc1[mt][nt]);
                    acc[mt][nt][0] += f0.x;
                    acc[mt][nt][1] += f0.y;
                    acc[mt][nt][2] += f1.x;
                    acc[mt][nt][3] += f1.y;
                    cc0[mt][nt] = 0u; cc1[mt][nt] = 0u;
                }
        }
    }

    // ---- epilogue ----
#pragma unroll
    for (int mt = 0; mt < 2; mt++) {
#pragma unroll
        for (int nt = 0; nt < 8; nt++) {
            int row = m0 + mbase + mt * 16 + g;
            int col = n0 + nbase + nt * 8 + 2 * t4;
            __half2 o0 = __floats2half2_rn(acc[mt][nt][0], acc[mt][nt][1]);
            __half2 o1 = __floats2half2_rn(acc[mt][nt][2], acc[mt][nt][3]);
            *(unsigned*)&g_Uh[(size_t)row * N_DIM + col] = *(unsigned*)&o0;
            *(unsigned*)&g_Uh[(size_t)(row + 8) * N_DIM + col] = *(unsigned*)&o1;
        }
    }

    // ---- publish: this (n,m) CTA's contribution to m-block blockIdx.y ----
    __threadfence();
    __syncthreads();
    if (tid == 0) atomicAdd(&g_cnt[blockIdx.y], 1u);
}

// ---------------------------------------------------------------------------
// Kernel 3: SRU scan (R9 double-buffer) gated on m-block progress.
// m-block y covers l-steps [8y, 8y+8). Group of PF=16 steps needs 2 blocks.
// ---------------------------------------------------------------------------
#define PF 16

__global__ void __launch_bounds__(64) sru_scan(const float* __restrict__ X,
                                               const float* __restrict__ C0,
                                               const float* __restrict__ Wc,
                                               const float* __restrict__ Bias,
                                               float* __restrict__ Out,
                                               int write_c) {
    int ch = blockIdx.x * 64 + threadIdx.x;  // 0..16383
    int d = ch & (D_DIM - 1);

    float fw = Wc[d], rw = Wc[D_DIM + d];
    float fb = Bias[d], rb = Bias[D_DIM + d];
    float c = C0[ch];

    float fwl = -fw * LOG2E, rwl = -rw * LOG2E;
    float fbl = -fb * LOG2E, rbl = -rb * LOG2E;

    const float SC = 1.7320508075688772f;
    const __half* up = g_Uh + (size_t)(ch >> 10) * N_DIM + 3 * d;
    const float* xp = X + ch;
    float* hp = Out + ch;

    const int US = B_DIM * N_DIM;
    const int XS = B_DIM * D_DIM;

    float bu0[2][PF], bu1[2][PF], bu2[2][PF], bx[2][PF];

    // wait for the first 16 l-steps (m-blocks 0,1), then preload group 0
    wait_mblock(0);
    wait_mblock(1);
#pragma unroll
    for (int j = 0; j < PF; j++) {
        const __half* u = up + (size_t)j * US;
        bu0[0][j] = __half2float(u[0]);
        bu1[0][j] = __half2float(u[1]);
        bu2[0][j] = __half2float(u[2]);
        bx[0][j]  = xp[(size_t)j * XS];
    }

#pragma unroll 2
    for (int l = 0; l < L_DIM; l += PF) {
        int p = (l / PF) & 1;
        if (l + PF < L_DIM) {
            int gl = l + PF;
            wait_mblock(gl >> 3);
            wait_mblock((gl >> 3) + 1);
#pragma unroll
            for (int j = 0; j < PF; j++) {
                const __half* u = up + (size_t)(PF + j) * US;
                bu0[p ^ 1][j] = __half2float(u[0]);
                bu1[p ^ 1][j] = __half2float(u[1]);
                bu2[p ^ 1][j] = __half2float(u[2]);
                bx[p ^ 1][j]  = xp[(size_t)(PF + j) * XS];
            }
        }
#pragma unroll
        for (int j = 0; j < PF; j++) {
            float u0 = bu0[p][j];
            float xv = bx[p][j] * SC;
            float a1 = fmaf(bu1[p][j], -LOG2E, fbl);
            float a2 = fmaf(bu2[p][j], -LOG2E, rbl);
            float f = rcpf(1.0f + ex2f(fmaf(c, fwl, a1)));
            float r = rcpf(1.0f + ex2f(fmaf(c, rwl, a2)));
            c = u0 + (c - u0) * f;
            hp[(size_t)j * XS] = xv + (c - xv) * r;
        }
        up += (size_t)PF * US;
        xp += (size_t)PF * XS;
        hp += (size_t)PF * XS;
    }
    if (write_c) Out[(size_t)L_DIM * B_DIM * D_DIM + ch] = c;
}

// ---------------------------------------------------------------------------
extern "C" void kernel_launch(void* const* d_in, const int* in_sizes, int n_in,
                              void* d_out, int out_size) {
    const float* x    = (const float*)d_in[0];
    const float* c0   = (const float*)d_in[1];
    const float* w    = (const float*)d_in[2];
    const float* wc   = (const float*)d_in[3];
    const float* bias = (const float*)d_in[4];
    float* out = (float*)d_out;

    int write_c = (out_size >= L_DIM * B_DIM * D_DIM + B_DIM * D_DIM) ? 1 : 0;

    static cudaStream_t s2 = nullptr;
    static cudaEvent_t e_init = nullptr, e_done = nullptr;
    static int init_done = 0;
    if (!init_done) {
        cudaFuncSetAttribute(gemm_f16, cudaFuncAttributeMaxDynamicSharedMemorySize,
                             GEMM_SMEM_BYTES);
        cudaStreamCreateWithFlags(&s2, cudaStreamNonBlocking);
        cudaEventCreateWithFlags(&e_init, cudaEventDisableTiming);
        cudaEventCreateWithFlags(&e_done, cudaEventDisableTiming);
        init_done = 1;
    }

    // stream 0: init counters -> convert -> transpose -> GEMM (single launch)
    init_cnt<<<1, NBLK_Y>>>();
    cudaEventRecord(e_init, 0);
    convert_x<<<(M_DIM * (K_DIM / 8)) / 256, 256>>>(x);
    transpose_w<<<dim3(N_DIM / 32, K_DIM / 32), dim3(32, 8)>>>(w);
    gemm_f16<<<dim3(NBLK_X, NBLK_Y), 256, GEMM_SMEM_BYTES>>>();

    // stream 2: scan runs concurrently, gated by device progress counters
    cudaStreamWaitEvent(s2, e_init, 0);
    sru_scan<<<(B_DIM * D_DIM) / 64, 64, 0, s2>>>(x, c0, wc, bias, out, write_c);

    cudaEventRecord(e_done, s2);
    cudaStreamWaitEvent(0, e_done, 0);
}

// round 15
// speedup vs baseline: 6.4604x; 6.4604x over previous
#include <cuda_runtime.h>
#include <cuda_fp16.h>

// ============================================================================
// SRU cell. L=2048, B=16, D=1024.  Serial pipeline (overlap abandoned).
//   u = x @ W  -> fp16 mma.sync; fp16 partials chained over 2 kt (4 mmas),
//   promoted to fp32 every other kt; two-phase mma issue (indep-first).
//   scan: R9 (16-deep double-buffered burst prefetch, approx sigmoid).
// ============================================================================

#define L_DIM 2048
#define B_DIM 16
#define D_DIM 1024
#define N_DIM 3072
#define K_DIM 1024
#define M_DIM 32768  // L*B

#define BM 128
#define BN 128
#define BK 32
#define STAGES 4
#define ROWSTR_H 40
#define KT (K_DIM / BK)
#define STAGE_H (2 * BM * ROWSTR_H)
#define GEMM_SMEM_BYTES (STAGES * STAGE_H * 2) // 81920

#define LOG2E 1.4426950408889634f

// Scratch (allocation-free rule: __device__ globals)
__device__ __half g_Xh[(size_t)M_DIM * K_DIM];  // X fp16 (64 MB)
__device__ __half g_Wh[N_DIM * K_DIM];          // W^T fp16 (6 MB)
__device__ __half g_Uh[(size_t)M_DIM * N_DIM];  // GEMM output u, fp16 (201 MB)

// ---------------------------------------------------------------------------
__device__ __forceinline__ unsigned smem_u32(const void* p) {
    unsigned a;
    asm("{ .reg .u64 t; cvta.to.shared.u64 t, %1; cvt.u32.u64 %0, t; }" : "=r"(a) : "l"(p));
    return a;
}

__device__ __forceinline__ void cp_async16(unsigned dst, const void* src) {
    asm volatile("cp.async.cg.shared.global [%0], [%1], 16;" :: "r"(dst), "l"(src));
}

__device__ __forceinline__ void ldmatrix_x4(unsigned& r0, unsigned& r1,
                                            unsigned& r2, unsigned& r3, unsigned addr) {
    asm volatile("ldmatrix.sync.aligned.m8n8.x4.shared.b16 {%0,%1,%2,%3}, [%4];"
                 : "=r"(r0), "=r"(r1), "=r"(r2), "=r"(r3) : "r"(addr));
}

__device__ __forceinline__ void mma_f16c(unsigned& c0, unsigned& c1,
                                         const unsigned* a, const unsigned* b) {
    asm volatile(
        "mma.sync.aligned.m16n8k16.row.col.f16.f16.f16.f16 "
        "{%0,%1}, {%2,%3,%4,%5}, {%6,%7}, {%0,%1};"
        : "+r"(c0), "+r"(c1)
        : "r"(a[0]), "r"(a[1]), "r"(a[2]), "r"(a[3]), "r"(b[0]), "r"(b[1]));
}

__device__ __forceinline__ float ex2f(float x) {
    float r; asm("ex2.approx.f32 %0, %1;" : "=f"(r) : "f"(x)); return r;
}
__device__ __forceinline__ float rcpf(float x) {
    float r; asm("rcp.approx.f32 %0, %1;" : "=f"(r) : "f"(x)); return r;
}

// ---------------------------------------------------------------------------
// Kernel 0: convert X -> fp16
// ---------------------------------------------------------------------------
__global__ void __launch_bounds__(256) convert_x(const float* __restrict__ X) {
    size_t i = ((size_t)blockIdx.x * 256 + threadIdx.x) * 8;
    float4 a = *(const float4*)(X + i);
    float4 b = *(const float4*)(X + i + 4);
    __half2 h0 = __floats2half2_rn(a.x, a.y);
    __half2 h1 = __floats2half2_rn(a.z, a.w);
    __half2 h2 = __floats2half2_rn(b.x, b.y);
    __half2 h3 = __floats2half2_rn(b.z, b.w);
    uint4 o;
    o.x = *(unsigned*)&h0; o.y = *(unsigned*)&h1;
    o.z = *(unsigned*)&h2; o.w = *(unsigned*)&h3;
    *(uint4*)(g_Xh + i) = o;
}

// ---------------------------------------------------------------------------
// Kernel 1: transpose W (K,N) -> W^T (N,K) fp16
// ---------------------------------------------------------------------------
__global__ void transpose_w(const float* __restrict__ W) {
    __shared__ float t[32][33];
    int n0 = blockIdx.x * 32, k0 = blockIdx.y * 32;
    int tx = threadIdx.x, ty = threadIdx.y;  // 32 x 8
#pragma unroll
    for (int i = 0; i < 32; i += 8)
        t[ty + i][tx] = W[(size_t)(k0 + ty + i) * N_DIM + n0 + tx];
    __syncthreads();
#pragma unroll
    for (int i = 0; i < 32; i += 8)
        g_Wh[(size_t)(n0 + ty + i) * K_DIM + k0 + tx] = __float2half_rn(t[tx][ty + i]);
}

// ---------------------------------------------------------------------------
// Kernel 2: fp16 GEMM. fp16 partials over 2 kt, fp32 promotion every other kt.
// Two-phase mma issue: all 16 independent chain-starts first, then the 16
// dependent chain-continuations (hides mma RAW latency).
// ---------------------------------------------------------------------------
__global__ void __launch_bounds__(256) gemm_f16() {
    extern __shared__ __half smem_h[];
    unsigned sbase = smem_u32(smem_h);

    int tid = threadIdx.x;
    int wid = tid >> 5;
    int lid = tid & 31;
    int g   = lid >> 2;
    int t4  = lid & 3;
    int q   = lid >> 3;
    int rr  = lid & 7;
    int warp_m = wid >> 1;
    int warp_n = wid & 1;
    int mbase = warp_m * 32;
    int nbase = warp_n * 64;

    int n0 = blockIdx.x * BN;
    int m0 = blockIdx.y * BM;

    const __half* Arow = g_Xh + (size_t)m0 * K_DIM;
    const __half* Brow = g_Wh + (size_t)n0 * K_DIM;
    const int B_OFF_H = BM * ROWSTR_H;

    float acc[2][8][4];
    unsigned cc0[2][8], cc1[2][8];
#pragma unroll
    for (int mt = 0; mt < 2; mt++)
#pragma unroll
        for (int nt = 0; nt < 8; nt++) {
#pragma unroll
            for (int i = 0; i < 4; i++) acc[mt][nt][i] = 0.0f;
            cc0[mt][nt] = 0u; cc1[mt][nt] = 0u;
        }

    auto load_stage = [&](int stage, int kc) {
        unsigned sA = sbase + (unsigned)(stage * STAGE_H) * 2u;
        unsigned sB = sA + (unsigned)B_OFF_H * 2u;
#pragma unroll
        for (int t = 0; t < 2; t++) {
            int j = tid + t * 256;
            int row = j >> 2;
            int c = j & 3;
            unsigned off = (unsigned)(row * ROWSTR_H + c * 8) * 2u;
            cp_async16(sA + off, Arow + (size_t)row * K_DIM + kc + c * 8);
            cp_async16(sB + off, Brow + (size_t)row * K_DIM + kc + c * 8);
        }
        asm volatile("cp.async.commit_group;" ::: "memory");
    };

    // one kt body; phase = kt&1 decides promotion
    auto kt_body = [&](int kt, int phase) {
        asm volatile("cp.async.wait_group %0;" :: "n"(STAGES - 2) : "memory");
        __syncthreads();

        if (kt + STAGES - 1 < KT)
            load_stage((kt + STAGES - 1) % STAGES, (kt + STAGES - 1) * BK);
        else
            asm volatile("cp.async.commit_group;" ::: "memory");

        unsigned stA = sbase + (unsigned)((kt % STAGES) * STAGE_H) * 2u;
        unsigned stB = stA + (unsigned)B_OFF_H * 2u;

        unsigned a[2][2][4];
        unsigned b[2][8][2];
#pragma unroll
        for (int kk = 0; kk < 2; kk++) {
#pragma unroll
            for (int mt = 0; mt < 2; mt++) {
                int row = mbase + mt * 16 + ((q & 1) << 3) + rr;
                int kh  = kk * 16 + (q >> 1) * 8;
                ldmatrix_x4(a[kk][mt][0], a[kk][mt][1], a[kk][mt][2], a[kk][mt][3],
                            stA + (unsigned)(row * ROWSTR_H + kh) * 2u);
            }
#pragma unroll
            for (int nt2 = 0; nt2 < 4; nt2++) {
                int row = nbase + nt2 * 16 + ((q >> 1) << 3) + rr;
                int kh  = kk * 16 + (q & 1) * 8;
                ldmatrix_x4(b[kk][nt2 * 2][0], b[kk][nt2 * 2][1],
                            b[kk][nt2 * 2 + 1][0], b[kk][nt2 * 2 + 1][1],
                            stB + (unsigned)(row * ROWSTR_H + kh) * 2u);
            }
        }

        // phase 1: 16 independent mmas (kk=0)
#pragma unroll
        for (int mt = 0; mt < 2; mt++)
#pragma unroll
            for (int nt = 0; nt < 8; nt++)
                mma_f16c(cc0[mt][nt], cc1[mt][nt], a[0][mt], b[0][nt]);
        // phase 2: 16 dependent mmas (kk=1) — each has 15 indep insts ahead
#pragma unroll
        for (int mt = 0; mt < 2; mt++)
#pragma unroll
            for (int nt = 0; nt < 8; nt++)
                mma_f16c(cc0[mt][nt], cc1[mt][nt], a[1][mt], b[1][nt]);

        if (phase) {
#pragma unroll
            for (int mt = 0; mt < 2; mt++)
#pragma unroll
                for (int nt = 0; nt < 8; nt++) {
                    float2 f0 = __half22float2(*(__half2*)&cc0[mt][nt]);
                    float2 f1 = __half22float2(*(__half2*)&cc1[mt][nt]);
                    acc[mt][nt][0] += f0.x;
                    acc[mt][nt][1] += f0.y;
                    acc[mt][nt][2] += f1.x;
                    acc[mt][nt][3] += f1.y;
                    cc0[mt][nt] = 0u; cc1[mt][nt] = 0u;
                }
        }
    };

#pragma unroll
    for (int s = 0; s < STAGES - 1; s++) load_stage(s, s * BK);

    for (int kt = 0; kt < KT; kt += 2) {   // unrolled by 2: phases compile-time
        kt_body(kt, 0);
        kt_body(kt + 1, 1);
    }

    // ---- epilogue ----
#pragma unroll
    for (int mt = 0; mt < 2; mt++) {
#pragma unroll
        for (int nt = 0; nt < 8; nt++) {
            int row = m0 + mbase + mt * 16 + g;
            int col = n0 + nbase + nt * 8 + 2 * t4;
            __half2 o0 = __floats2half2_rn(acc[mt][nt][0], acc[mt][nt][1]);
            __half2 o1 = __floats2half2_rn(acc[mt][nt][2], acc[mt][nt][3]);
            *(unsigned*)&g_Uh[(size_t)row * N_DIM + col] = *(unsigned*)&o0;
            *(unsigned*)&g_Uh[(size_t)(row + 8) * N_DIM + col] = *(unsigned*)&o1;
        }
    }
}

// ---------------------------------------------------------------------------
// Kernel 3: SRU scan (R9 exact). 16-deep double-buffered burst prefetch.
// ---------------------------------------------------------------------------
#define PF 16

__global__ void __launch_bounds__(64) sru_scan(const float* __restrict__ X,
                                               const float* __restrict__ C0,
                                               const float* __restrict__ Wc,
                                               const float* __restrict__ Bias,
                                               float* __restrict__ Out,
                                               int write_c) {
    int ch = blockIdx.x * 64 + threadIdx.x;  // 0..16383
    int d = ch & (D_DIM - 1);

    float fw = Wc[d], rw = Wc[D_DIM + d];
    float fb = Bias[d], rb = Bias[D_DIM + d];
    float c = C0[ch];

    float fwl = -fw * LOG2E, rwl = -rw * LOG2E;
    float fbl = -fb * LOG2E, rbl = -rb * LOG2E;

    const float SC = 1.7320508075688772f;
    const __half* up = g_Uh + (size_t)(ch >> 10) * N_DIM + 3 * d;
    const float* xp = X + ch;
    float* hp = Out + ch;

    const int US = B_DIM * N_DIM;
    const int XS = B_DIM * D_DIM;

    float bu0[2][PF], bu1[2][PF], bu2[2][PF], bx[2][PF];

#pragma unroll
    for (int j = 0; j < PF; j++) {
        const __half* u = up + (size_t)j * US;
        bu0[0][j] = __half2float(u[0]);
        bu1[0][j] = __half2float(u[1]);
        bu2[0][j] = __half2float(u[2]);
        bx[0][j]  = xp[(size_t)j * XS];
    }

#pragma unroll 2
    for (int l = 0; l < L_DIM; l += PF) {
        int p = (l / PF) & 1;
        if (l + PF < L_DIM) {
#pragma unroll
            for (int j = 0; j < PF; j++) {
                const __half* u = up + (size_t)(PF + j) * US;
                bu0[p ^ 1][j] = __half2float(u[0]);
                bu1[p ^ 1][j] = __half2float(u[1]);
                bu2[p ^ 1][j] = __half2float(u[2]);
                bx[p ^ 1][j]  = xp[(size_t)(PF + j) * XS];
            }
        }
#pragma unroll
        for (int j = 0; j < PF; j++) {
            float u0 = bu0[p][j];
            float xv = bx[p][j] * SC;
            float a1 = fmaf(bu1[p][j], -LOG2E, fbl);
            float a2 = fmaf(bu2[p][j], -LOG2E, rbl);
            float f = rcpf(1.0f + ex2f(fmaf(c, fwl, a1)));
            float r = rcpf(1.0f + ex2f(fmaf(c, rwl, a2)));
            c = u0 + (c - u0) * f;
            hp[(size_t)j * XS] = xv + (c - xv) * r;
        }
        up += (size_t)PF * US;
        xp += (size_t)PF * XS;
        hp += (size_t)PF * XS;
    }
    if (write_c) Out[(size_t)L_DIM * B_DIM * D_DIM + ch] = c;
}

// ---------------------------------------------------------------------------
extern "C" void kernel_launch(void* const* d_in, const int* in_sizes, int n_in,
                              void* d_out, int out_size) {
    const float* x    = (const float*)d_in[0];
    const float* c0   = (const float*)d_in[1];
    const float* w    = (const float*)d_in[2];
    const float* wc   = (const float*)d_in[3];
    const float* bias = (const float*)d_in[4];
    float* out = (float*)d_out;

    int write_c = (out_size >= L_DIM * B_DIM * D_DIM + B_DIM * D_DIM) ? 1 : 0;

    static int init_done = 0;
    if (!init_done) {
        cudaFuncSetAttribute(gemm_f16, cudaFuncAttributeMaxDynamicSharedMemorySize,
                             GEMM_SMEM_BYTES);
        init_done = 1;
    }

    convert_x<<<(M_DIM * (K_DIM / 8)) / 256, 256>>>(x);
    transpose_w<<<dim3(N_DIM / 32, K_DIM / 32), dim3(32, 8)>>>(w);
    gemm_f16<<<dim3(N_DIM / BN, M_DIM / BM), 256, GEMM_SMEM_BYTES>>>();
    sru_scan<<<(B_DIM * D_DIM) / 64, 64>>>(x, c0, wc, bias, out, write_c);
}